// round 1
// baseline (speedup 1.0000x reference)
#include <cuda_runtime.h>
#include <math.h>

#define NMAT_X 32768
#define C_CLS  128
#define NDIM   64
#define NSQ    4096          // 64*64
#define PITCH  65            // smem pitch (odd -> conflict-free columns)
#define MAXSWEEP 13

// ---- scratch (device globals; no runtime allocation allowed) ----
__device__ float g_logX[134217728];   // 32768 * 4096  (512 MB)
__device__ float g_logP[C_CLS * NSQ];
__device__ float g_Asym[C_CLS * NSQ];
__device__ float g_offs[C_CLS];

// =====================================================================
// A_sym = tril(A,-1) + tril(A,-1)^T + diag(A)
// =====================================================================
__global__ __launch_bounds__(256) void make_asym_k(const float* __restrict__ A,
                                                   float* __restrict__ S) {
    int c = blockIdx.x;
    const float* Ac = A + (size_t)c * NSQ;
    float* Sc = S + (size_t)c * NSQ;
    for (int t = threadIdx.x; t < NSQ; t += 256) {
        int i = t >> 6, j = t & 63;
        float v;
        if (i == j)      v = Ac[t];
        else if (i > j)  v = Ac[i * 64 + j];
        else             v = Ac[j * 64 + i];
        Sc[t] = v;
    }
}

// =====================================================================
// Batched Jacobi eigensolver + logm reconstruction.
// One block (256 threads) per 64x64 SPD matrix.
// =====================================================================
__device__ __forceinline__ void tourney_pair(int r, int i, int* p, int* q) {
    // round-robin tournament over 64 players, player 0 fixed. r in [0,62], i in [0,31]
    if (i == 0) { *p = 0; *q = 1 + r; }
    else {
        *p = 1 + (r + i) % 63;
        *q = 1 + (r - i + 63) % 63;
    }
}

__global__ __launch_bounds__(256) void jacobi_logm_k(const float* __restrict__ in,
                                                     float* __restrict__ out) {
    __shared__ float As[NDIM * PITCH];
    __shared__ float Vs[NDIM * PITCH];
    __shared__ float csA[32], snA[32];
    __shared__ int   ppA[32], qqA[32];
    __shared__ float wsum[8];
    __shared__ float fro2v;
    __shared__ int   convflag;
    __shared__ float ev[64];

    const int tid = threadIdx.x;
    const size_t m = blockIdx.x;
    const float* Xm = in + m * (size_t)NSQ;

    // ---- load A, init V = I, accumulate ||A||_F^2 ----
    float part = 0.f;
    for (int t = tid; t < NSQ; t += 256) {
        int i = t >> 6, j = t & 63;
        float v = Xm[t];
        As[i * PITCH + j] = v;
        Vs[i * PITCH + j] = (i == j) ? 1.f : 0.f;
        part += v * v;
    }
    #pragma unroll
    for (int o = 16; o; o >>= 1) part += __shfl_down_sync(0xffffffffu, part, o);
    if ((tid & 31) == 0) wsum[tid >> 5] = part;
    __syncthreads();
    if (tid == 0) {
        float s = 0.f;
        #pragma unroll
        for (int w = 0; w < 8; ++w) s += wsum[w];
        fro2v = s;
        convflag = 0;
    }
    __syncthreads();

    // ---- Jacobi sweeps ----
    for (int sweep = 0; sweep < MAXSWEEP; ++sweep) {
        if (sweep >= 4) {
            // deterministic off-diagonal norm reduction
            float po = 0.f;
            for (int t = tid; t < NSQ; t += 256) {
                int i = t >> 6, j = t & 63;
                if (i != j) { float v = As[i * PITCH + j]; po += v * v; }
            }
            #pragma unroll
            for (int o = 16; o; o >>= 1) po += __shfl_down_sync(0xffffffffu, po, o);
            if ((tid & 31) == 0) wsum[tid >> 5] = po;
            __syncthreads();
            if (tid == 0) {
                float s = 0.f;
                #pragma unroll
                for (int w = 0; w < 8; ++w) s += wsum[w];
                convflag = (s <= 1e-10f * fro2v) ? 1 : 0;
            }
            __syncthreads();
            if (convflag) break;
        }

        for (int r = 0; r < 63; ++r) {
            // --- phase 1: 32 rotation params (one warp) ---
            if (tid < 32) {
                int p, q;
                tourney_pair(r, tid, &p, &q);
                ppA[tid] = p; qqA[tid] = q;
                float app = As[p * PITCH + p];
                float aqq = As[q * PITCH + q];
                float apq = As[p * PITCH + q];
                float c = 1.f, s = 0.f;
                if (fabsf(apq) > 1e-30f) {
                    float tau = (aqq - app) / (2.0f * apq);
                    float t = 1.0f / (fabsf(tau) + sqrtf(1.0f + tau * tau));
                    if (tau < 0.f) t = -t;
                    c = rsqrtf(1.f + t * t);
                    s = t * c;
                }
                csA[tid] = c; snA[tid] = s;
            }
            __syncthreads();

            // --- phase 2a: A <- J^T A J, 1024 disjoint 2x2 blocks ---
            {
                const int ri = tid >> 3;                 // this thread's row-pair
                const int p1 = ppA[ri], q1 = qqA[ri];
                const float c1 = csA[ri], s1 = snA[ri];
                const int cib = (tid & 7) * 4;
                #pragma unroll
                for (int it = 0; it < 4; ++it) {
                    const int ci = cib + it;
                    const int p2 = ppA[ci], q2 = qqA[ci];
                    const float c2 = csA[ci], s2 = snA[ci];
                    float a00 = As[p1 * PITCH + p2];
                    float a01 = As[p1 * PITCH + q2];
                    float a10 = As[q1 * PITCH + p2];
                    float a11 = As[q1 * PITCH + q2];
                    float t00 = c1 * a00 - s1 * a10;
                    float t01 = c1 * a01 - s1 * a11;
                    float t10 = s1 * a00 + c1 * a10;
                    float t11 = s1 * a01 + c1 * a11;
                    As[p1 * PITCH + p2] = c2 * t00 - s2 * t01;
                    As[p1 * PITCH + q2] = s2 * t00 + c2 * t01;
                    As[q1 * PITCH + p2] = c2 * t10 - s2 * t11;
                    As[q1 * PITCH + q2] = s2 * t10 + c2 * t11;
                }
            }
            // --- phase 2b: V <- V J (columns p,q) ---
            {
                const int pi = tid >> 3;
                const int p = ppA[pi], q = qqA[pi];
                const float c = csA[pi], s = snA[pi];
                const int rb = tid & 7;
                #pragma unroll
                for (int it = 0; it < 8; ++it) {
                    const int row = rb + 8 * it;
                    float vp = Vs[row * PITCH + p];
                    float vq = Vs[row * PITCH + q];
                    Vs[row * PITCH + p] = c * vp - s * vq;
                    Vs[row * PITCH + q] = s * vp + c * vq;
                }
            }
            __syncthreads();
        }
    }

    // ---- eigenvalue logs ----
    if (tid < 64) ev[tid] = logf(fmaxf(As[tid * PITCH + tid], 1e-12f));
    __syncthreads();

    // ---- W = V * diag(log lambda), overwrite As ----
    for (int t = tid; t < NSQ; t += 256) {
        int i = t >> 6, k = t & 63;
        As[i * PITCH + k] = Vs[i * PITCH + k] * ev[k];
    }
    __syncthreads();

    // ---- logX = W V^T, 4x4 register tile per thread, float4 stores ----
    {
        const int bi = tid >> 4;   // 0..15
        const int bj = tid & 15;   // 0..15
        float acc[4][4];
        #pragma unroll
        for (int u = 0; u < 4; ++u)
            #pragma unroll
            for (int v = 0; v < 4; ++v) acc[u][v] = 0.f;
        for (int k = 0; k < 64; ++k) {
            float wv[4], vv[4];
            #pragma unroll
            for (int u = 0; u < 4; ++u) wv[u] = As[(4 * bi + u) * PITCH + k];
            #pragma unroll
            for (int v = 0; v < 4; ++v) vv[v] = Vs[(4 * bj + v) * PITCH + k];
            #pragma unroll
            for (int u = 0; u < 4; ++u)
                #pragma unroll
                for (int v = 0; v < 4; ++v) acc[u][v] += wv[u] * vv[v];
        }
        float* outm = out + m * (size_t)NSQ;
        #pragma unroll
        for (int u = 0; u < 4; ++u) {
            float4 o = make_float4(acc[u][0], acc[u][1], acc[u][2], acc[u][3]);
            *reinterpret_cast<float4*>(&outm[(4 * bi + u) * 64 + 4 * bj]) = o;
        }
    }
}

// =====================================================================
// offs[c] = <logP_c, Asym_c>
// =====================================================================
__global__ __launch_bounds__(256) void make_offs_k(const float* __restrict__ LP,
                                                   const float* __restrict__ S,
                                                   float* __restrict__ offs) {
    __shared__ float ws[8];
    int c = blockIdx.x;
    float part = 0.f;
    for (int t = threadIdx.x; t < NSQ; t += 256)
        part += LP[(size_t)c * NSQ + t] * S[(size_t)c * NSQ + t];
    #pragma unroll
    for (int o = 16; o; o >>= 1) part += __shfl_down_sync(0xffffffffu, part, o);
    if ((threadIdx.x & 31) == 0) ws[threadIdx.x >> 5] = part;
    __syncthreads();
    if (threadIdx.x == 0) {
        float s = 0.f;
        #pragma unroll
        for (int w = 0; w < 8; ++w) s += ws[w];
        offs[c] = s;
    }
}

// =====================================================================
// out[n,c] = sum_k logX[n,k] * Asym[c,k] - offs[c]
// Tile: 128 n-rows x 128 classes per block, 256 threads, 8x8 per thread
// Strided register ownership (rows: ti+16u, cols: tj+16v) -> conflict-free LDS
// =====================================================================
__global__ __launch_bounds__(256) void logits_gemm_k(const float* __restrict__ LX,
                                                     const float* __restrict__ B,
                                                     const float* __restrict__ offs,
                                                     float* __restrict__ out) {
    __shared__ float Xs[128][33];
    __shared__ float Bs[128][33];
    const int tid = threadIdx.x;
    const int n0 = blockIdx.x * 128;
    const int ti = tid >> 4;   // 0..15
    const int tj = tid & 15;   // 0..15

    float acc[8][8];
    #pragma unroll
    for (int u = 0; u < 8; ++u)
        #pragma unroll
        for (int v = 0; v < 8; ++v) acc[u][v] = 0.f;

    for (int k0 = 0; k0 < NSQ; k0 += 32) {
        // cooperative load of 128x32 tiles (float4 global reads)
        #pragma unroll
        for (int it = 0; it < 4; ++it) {
            int f = tid + it * 256;          // 0..1023
            int row = f >> 3;
            int c4 = (f & 7) * 4;
            float4 x = *reinterpret_cast<const float4*>(
                &LX[(size_t)(n0 + row) * NSQ + k0 + c4]);
            Xs[row][c4] = x.x; Xs[row][c4 + 1] = x.y;
            Xs[row][c4 + 2] = x.z; Xs[row][c4 + 3] = x.w;
            float4 b = *reinterpret_cast<const float4*>(
                &B[(size_t)row * NSQ + k0 + c4]);
            Bs[row][c4] = b.x; Bs[row][c4 + 1] = b.y;
            Bs[row][c4 + 2] = b.z; Bs[row][c4 + 3] = b.w;
        }
        __syncthreads();

        #pragma unroll 4
        for (int kk = 0; kk < 32; ++kk) {
            float xr[8], bc[8];
            #pragma unroll
            for (int u = 0; u < 8; ++u) xr[u] = Xs[ti + 16 * u][kk];
            #pragma unroll
            for (int v = 0; v < 8; ++v) bc[v] = Bs[tj + 16 * v][kk];
            #pragma unroll
            for (int u = 0; u < 8; ++u)
                #pragma unroll
                for (int v = 0; v < 8; ++v) acc[u][v] += xr[u] * bc[v];
        }
        __syncthreads();
    }

    float offv[8];
    #pragma unroll
    for (int v = 0; v < 8; ++v) offv[v] = offs[tj + 16 * v];
    #pragma unroll
    for (int u = 0; u < 8; ++u) {
        size_t rowoff = (size_t)(n0 + ti + 16 * u) * C_CLS;
        #pragma unroll
        for (int v = 0; v < 8; ++v)
            out[rowoff + tj + 16 * v] = acc[u][v] - offv[v];
    }
}

// =====================================================================
extern "C" void kernel_launch(void* const* d_in, const int* in_sizes, int n_in,
                              void* d_out, int out_size) {
    // inputs in metadata order: X (32768*4096), P (128*4096), A (128*4096)
    const float* X = (const float*)d_in[0];
    const float* P = (const float*)d_in[1];
    const float* A = (const float*)d_in[2];
    // robustness: X is the uniquely-largest input
    if (n_in == 3) {
        int xi = 0;
        for (int i = 1; i < 3; ++i) if (in_sizes[i] > in_sizes[xi]) xi = i;
        if (xi != 0) {
            // keep relative order of the remaining two as (P, A)
            const float* ins[3] = {(const float*)d_in[0], (const float*)d_in[1],
                                   (const float*)d_in[2]};
            X = ins[xi];
            int k = 0;
            const float* rest[2];
            for (int i = 0; i < 3; ++i) if (i != xi) rest[k++] = ins[i];
            P = rest[0]; A = rest[1];
        }
    }
    float* out = (float*)d_out;

    float *p_logX = nullptr, *p_logP = nullptr, *p_Asym = nullptr, *p_offs = nullptr;
    cudaGetSymbolAddress((void**)&p_logX, g_logX);
    cudaGetSymbolAddress((void**)&p_logP, g_logP);
    cudaGetSymbolAddress((void**)&p_Asym, g_Asym);
    cudaGetSymbolAddress((void**)&p_offs, g_offs);

    make_asym_k<<<C_CLS, 256>>>(A, p_Asym);
    jacobi_logm_k<<<C_CLS, 256>>>(P, p_logP);
    jacobi_logm_k<<<NMAT_X, 256>>>(X, p_logX);
    make_offs_k<<<C_CLS, 256>>>(p_logP, p_Asym, p_offs);
    logits_gemm_k<<<NMAT_X / 128, 256>>>(p_logX, p_Asym, p_offs, out);
}